// round 10
// baseline (speedup 1.0000x reference)
#include <cuda_runtime.h>
#include <cuda_fp16.h>
#include <cstdint>

// Problem constants
#define NB   16384   // batch rows
#define ND   1024    // model dim
#define NF   8192    // features
#define KTOP 30
#define NCAND 40     // approx candidates kept per row (fp16-accum ranking margin)

// ---------------- device scratch (no allocations allowed) ----------------
__device__ unsigned short g_preh[(size_t)NB * NF];  // approx scores, fp16 bits, 256 MB
__device__ float g_dwt[(size_t)NF * ND];    // dec_w transposed [F, D], 32 MB
__device__ float g_c[NF];                   // folded bias: enc_b - enc_w @ dec_b
__device__ int   g_cand[(size_t)NB * NCAND];// candidate indices (approx top-40)
__device__ float g_wv[(size_t)NB * 32];     // exact relu(top-30) values
__device__ int   g_wi[(size_t)NB * 32];     // exact top-30 indices
// fp16 copies
__device__ __half g_a0[(size_t)NB * ND];
__device__ __half g_b0[(size_t)NF * ND];

// ======================= PTX helpers (baseline sm_80+ features only) =======================
__device__ __forceinline__ uint32_t smem_to_u32(const void* smem_ptr) {
    uint32_t addr;
    asm("{ .reg .u64 tmp; cvta.to.shared.u64 tmp, %1; cvt.u32.u64 %0, tmp; }"
        : "=r"(addr) : "l"(smem_ptr));
    return addr;
}

__device__ __forceinline__ void cp_async16(uint32_t dst, const void* src) {
    asm volatile("cp.async.cg.shared.global [%0], [%1], 16;"
                 :: "r"(dst), "l"(src));
}
#define CP_COMMIT() asm volatile("cp.async.commit_group;" ::: "memory")
#define CP_WAIT(n)  asm volatile("cp.async.wait_group %0;" :: "n"(n) : "memory")

__device__ __forceinline__ void ldsm4(uint32_t r[4], uint32_t addr) {
    asm volatile("ldmatrix.sync.aligned.m8n8.x4.shared.b16 {%0,%1,%2,%3}, [%4];"
                 : "=r"(r[0]), "=r"(r[1]), "=r"(r[2]), "=r"(r[3]) : "r"(addr));
}

// fp16 MMA with fp16 accumulate: m16n8k16 (Volta-class, lowest-risk legacy path)
__device__ __forceinline__ void mma_f16acc(uint32_t d[2], const uint32_t a[4],
                                           uint32_t b0, uint32_t b1) {
    asm volatile(
        "mma.sync.aligned.m16n8k16.row.col.f16.f16.f16.f16 "
        "{%0,%1}, {%2,%3,%4,%5}, {%6,%7}, {%0,%1};"
        : "+r"(d[0]), "+r"(d[1])
        : "r"(a[0]), "r"(a[1]), "r"(a[2]), "r"(a[3]), "r"(b0), "r"(b1));
}

// ---------------- fp32 -> fp16 convert ----------------
__global__ void tof16_kernel(const float4* __restrict__ in,
                             __half* __restrict__ o0, int n4) {
    int i   = blockIdx.x * blockDim.x + threadIdx.x;
    int str = gridDim.x * blockDim.x;
    for (; i < n4; i += str) {
        float4 v = in[i];
        uint2 u0;
        ((__half2*)&u0)[0] = __floats2half2_rn(v.x, v.y);
        ((__half2*)&u0)[1] = __floats2half2_rn(v.z, v.w);
        *(uint2*)(o0 + (size_t)4 * i) = u0;
    }
}

// ---------------- c[f] = enc_b[f] - sum_d enc_w[f,d] * dec_b[d] ----------------
__global__ void compute_c_kernel(const float* __restrict__ enc_w,
                                 const float* __restrict__ enc_b,
                                 const float* __restrict__ dec_b) {
    int f    = blockIdx.x * 8 + (threadIdx.x >> 5);
    int lane = threadIdx.x & 31;
    const float* wrow = enc_w + (size_t)f * ND;
    float s = 0.f;
    #pragma unroll 8
    for (int d = lane; d < ND; d += 32) s += wrow[d] * dec_b[d];
    #pragma unroll
    for (int off = 16; off; off >>= 1) s += __shfl_down_sync(0xffffffffu, s, off);
    if (lane == 0) g_c[f] = enc_b[f] - s;
}

// ---------------- transpose dec_w [D,F] -> g_dwt [F,D] ----------------
__global__ void transpose_kernel(const float* __restrict__ dec_w) {
    __shared__ float tile[32][33];
    int f0 = blockIdx.x * 32, d0 = blockIdx.y * 32;
    int tx = threadIdx.x, ty = threadIdx.y;   // 32 x 8
    #pragma unroll
    for (int q = 0; q < 4; q++)
        tile[ty + q * 8][tx] = dec_w[(size_t)(d0 + ty + q * 8) * NF + f0 + tx];
    __syncthreads();
    #pragma unroll
    for (int q = 0; q < 4; q++)
        g_dwt[(size_t)(f0 + ty + q * 8) * ND + d0 + tx] = tile[tx][ty + q * 8];
}

// =====================================================================
// fp16-accum mma.sync GEMM (K=1024):  g_preh ~= f16(x @ enc_w^T + c)
// + zero-fill of the sparse output tile (free on DRAM headroom)
// CTA 128x128, 8 warps (2Mx4N, warp tile 64x32), BK=32, 4-stage cp.async
// =====================================================================
#define BKC    32
#define ROWB   80                    // smem row stride bytes (64 data + 16 pad)
#define ASTG   (128 * ROWB)          // 10240 bytes
#define STGB   (2 * ASTG)            // 20480 bytes per stage (A then B)
#define GEMM_SMEM (4 * STGB)         // 81920
#define NCHUNK (ND / BKC)            // 32

__device__ __forceinline__ void load_stage(uint32_t sm,
                                           const __half* __restrict__ ga,
                                           const __half* __restrict__ gb,
                                           int kbase, int tid) {
    #pragma unroll
    for (int h = 0; h < 2; h++) {
        int c = tid + h * 256;           // 0..511
        int row = c >> 2, kc = c & 3;
        cp_async16(sm + row * ROWB + kc * 16,
                   ga + (size_t)row * ND + kbase + kc * 8);
    }
    #pragma unroll
    for (int h = 0; h < 2; h++) {
        int c = tid + h * 256;
        int row = c >> 2, kc = c & 3;
        cp_async16(sm + ASTG + row * ROWB + kc * 16,
                   gb + (size_t)row * ND + kbase + kc * 8);
    }
}

__global__ __launch_bounds__(256)
void tc_gemm_kernel(float* __restrict__ sparse) {
    extern __shared__ __align__(128) char smem[];
    const uint32_t base = smem_to_u32(smem);
    const int tid  = threadIdx.x;
    const int lane = tid & 31;
    const int wid  = tid >> 5;
    const int wm   = wid >> 2;       // 0..1
    const int wn   = wid & 3;        // 0..3
    const int m0 = blockIdx.y * 128;
    const int n0 = blockIdx.x * 128;

    const __half* AP = g_a0 + (size_t)m0 * ND;
    const __half* BP = g_b0 + (size_t)n0 * ND;

    // prologue: stages 0..2
    #pragma unroll
    for (int q = 0; q < 3; q++) {
        load_stage(base + q * STGB, AP, BP, q * BKC, tid);
        CP_COMMIT();
    }

    // zero-fill this CTA's 128x128 sparse tile while loads are in flight
    {
        float4 z4 = make_float4(0.f, 0.f, 0.f, 0.f);
        float4* sp = (float4*)(sparse + (size_t)m0 * NF + n0);
        #pragma unroll
        for (int q = 0; q < 16; q++) {
            int u = q * 256 + tid;
            int r = u >> 5, sl = u & 31;      // 32 float4 slots per 128-col row
            sp[(size_t)r * (NF / 4) + sl] = z4;
        }
    }

    uint32_t acc[4][4][2] = {};   // fp16x2 accumulators (zero bits == +0.0h)

    // precomputed ldmatrix lane-address components
    const uint32_t a_row  = (uint32_t)(wm * 64 + (lane & 15)) * ROWB
                          + (uint32_t)(lane >> 4) * 16;
    const int g  = lane >> 3, r8 = lane & 7;
    const uint32_t b_row  = ASTG
        + (uint32_t)(wn * 32 + ((g >> 1) * 8) + r8) * ROWB
        + (uint32_t)(g & 1) * 16;

    for (int q = 0; q < NCHUNK; q++) {
        const uint32_t sb = base + (uint32_t)(q & 3) * STGB;
        CP_WAIT(2);
        __syncthreads();

        #pragma unroll
        for (int k16 = 0; k16 < 2; k16++) {
            uint32_t a[4][4], b[2][4];
            #pragma unroll
            for (int mi = 0; mi < 4; mi++)
                ldsm4(a[mi], sb + a_row + mi * 16 * ROWB + k16 * 32);
            #pragma unroll
            for (int nj = 0; nj < 2; nj++)
                ldsm4(b[nj], sb + b_row + nj * 16 * ROWB + k16 * 32);
            #pragma unroll
            for (int mi = 0; mi < 4; mi++) {
                #pragma unroll
                for (int nj = 0; nj < 2; nj++) {
                    mma_f16acc(acc[mi][nj * 2 + 0], a[mi], b[nj][0], b[nj][1]);
                    mma_f16acc(acc[mi][nj * 2 + 1], a[mi], b[nj][2], b[nj][3]);
                }
            }
        }

        if (q + 3 < NCHUNK) {
            int qq = q + 3;
            load_stage(base + (uint32_t)(qq & 3) * STGB, AP, BP, qq * BKC, tid);
        }
        CP_COMMIT();
    }

    // epilogue: acc + folded bias (fp32 add) -> fp16 bits in g_preh
    const int lr = lane >> 2;
    const int lc = (lane & 3) * 2;
    #pragma unroll
    for (int j = 0; j < 4; j++) {
        const int col = n0 + wn * 32 + j * 8 + lc;
        const float cx = g_c[col], cy = g_c[col + 1];
        #pragma unroll
        for (int mi = 0; mi < 4; mi++) {
            const int r0 = m0 + wm * 64 + mi * 16 + lr;
            __half2 h0 = *(__half2*)&acc[mi][j][0];   // (lr, lc), (lr, lc+1)
            __half2 h1 = *(__half2*)&acc[mi][j][1];   // (lr+8, lc), (lr+8, lc+1)
            __half2 o0 = __floats2half2_rn(__half2float(h0.x) + cx,
                                           __half2float(h0.y) + cy);
            __half2 o1 = __floats2half2_rn(__half2float(h1.x) + cx,
                                           __half2float(h1.y) + cy);
            *(uint32_t*)&g_preh[(size_t)r0 * NF + col]       = *(uint32_t*)&o0;
            *(uint32_t*)&g_preh[(size_t)(r0 + 8) * NF + col] = *(uint32_t*)&o1;
        }
    }
}

// ---------------- approx top-40 per row (32-bit packed keys) ----------------
__global__ __launch_bounds__(256)
void topk_kernel() {
    const int row = blockIdx.x;
    const int tid = threadIdx.x;
    const uint4* pre = (const uint4*)(g_preh + (size_t)row * NF);

    // pack: (key16 << 13) | (8191 - gidx); key16 = order-preserving fp16 map
    uint32_t pk[32];
    #pragma unroll
    for (int v = 0; v < 4; v++) {
        uint4 u = pre[v * 256 + tid];
        uint32_t rr[4] = {u.x, u.y, u.z, u.w};
        #pragma unroll
        for (int p = 0; p < 4; p++) {
            uint32_t lo = rr[p] & 0xFFFFu, hi = rr[p] >> 16;
            lo = (lo & 0x8000u) ? (~lo & 0xFFFFu) : (lo | 0x8000u);
            hi = (hi & 0x8000u) ? (~hi & 0xFFFFu) : (hi | 0x8000u);
            uint32_t g0 = (uint32_t)(v * 2048 + tid * 8 + p * 2);
            pk[v * 8 + p * 2 + 0] = (lo << 13) | (8191u - g0);
            pk[v * 8 + p * 2 + 1] = (hi << 13) | (8191u - (g0 + 1));
        }
    }

    uint32_t live = 0xFFFFFFFFu;
    uint32_t best = 0;
    #pragma unroll
    for (int i = 0; i < 32; i++) best = max(best, pk[i]);

    __shared__ uint32_t swarp[8];
    __shared__ uint32_t swin;
    __shared__ int winI[NCAND];

    for (int t = 0; t < NCAND; t++) {
        uint32_t p = best;
        #pragma unroll
        for (int off = 16; off; off >>= 1)
            p = max(p, __shfl_down_sync(0xffffffffu, p, off));
        if ((tid & 31) == 0) swarp[tid >> 5] = p;
        __syncthreads();
        if (tid < 32) {
            uint32_t q = (tid < 8) ? swarp[tid] : 0u;
            #pragma unroll
            for (int off = 4; off; off >>= 1)
                q = max(q, __shfl_down_sync(0xffffffffu, q, off));
            if (tid == 0) swin = q;
        }
        __syncthreads();
        const uint32_t w = swin;
        const uint32_t gidx = 8191u - (w & 0x1FFFu);
        if (tid == (int)((gidx & 2047u) >> 3)) {
            const int slot = (int)((gidx >> 11) * 8 + (gidx & 7u));
            live &= ~(1u << slot);
            winI[t] = (int)gidx;
            best = 0;
            #pragma unroll
            for (int i = 0; i < 32; i++)
                if ((live >> i) & 1u) best = max(best, pk[i]);
        }
        __syncthreads();
    }

    if (tid < NCAND) g_cand[(size_t)row * NCAND + tid] = winI[tid];
}

// ---------------- exact fp32 rerank of 40 candidates -> top-30 ----------------
__global__ __launch_bounds__(256)
void rerank_kernel(const float* __restrict__ x,
                   const float* __restrict__ enc_w,
                   float* __restrict__ sparse) {
    __shared__ float4 xs[ND / 4];
    __shared__ float  sc[NCAND];
    __shared__ int    si[NCAND];
    __shared__ int    cnt;
    const int row = blockIdx.x;
    const int tid = threadIdx.x;
    const int wid = tid >> 5, lane = tid & 31;

    xs[tid] = ((const float4*)(x + (size_t)row * ND))[tid];
    if (tid == 0) cnt = 0;
    __syncthreads();

    for (int c = wid; c < NCAND; c += 8) {
        const int f = g_cand[(size_t)row * NCAND + c];
        const float4* wr = (const float4*)(enc_w + (size_t)f * ND);
        float s = 0.f;
        #pragma unroll
        for (int j = lane; j < ND / 4; j += 32) {
            float4 wv = wr[j], xv = xs[j];
            s += wv.x * xv.x + wv.y * xv.y + wv.z * xv.z + wv.w * xv.w;
        }
        #pragma unroll
        for (int off = 16; off; off >>= 1) s += __shfl_down_sync(0xffffffffu, s, off);
        if (lane == 0) { sc[c] = s + g_c[f]; si[c] = f; }
    }
    __syncthreads();

    if (tid < NCAND) {
        const float v = sc[tid];
        const int   f = si[tid];
        int rank = 0;
        #pragma unroll
        for (int j = 0; j < NCAND; j++)
            rank += (sc[j] > v) || (sc[j] == v && si[j] < f);
        if (rank < KTOP) {
            const float rv = fmaxf(v, 0.f);
            sparse[(size_t)row * NF + f] = rv;
            int slot = atomicAdd(&cnt, 1);
            g_wv[(size_t)row * 32 + slot] = rv;
            g_wi[(size_t)row * 32 + slot] = f;
        }
    }
}

// ---------------- decode: recon[row,:] = dec_b + sum_k v_k * dec_wT[idx_k,:] ----------------
__global__ __launch_bounds__(256)
void decode_kernel(const float* __restrict__ dec_b, float* __restrict__ recon) {
    __shared__ float sv[KTOP];
    __shared__ int   si[KTOP];
    const int row = blockIdx.x;
    const int tid = threadIdx.x;
    if (tid < KTOP) {
        sv[tid] = g_wv[(size_t)row * 32 + tid];
        si[tid] = g_wi[(size_t)row * 32 + tid];
    }
    __syncthreads();

    const int d = tid * 4;
    float4 acc = *(const float4*)(dec_b + d);
    #pragma unroll 5
    for (int k = 0; k < KTOP; k++) {
        float v = sv[k];
        const float4 w = *(const float4*)(g_dwt + (size_t)si[k] * ND + d);
        acc.x = fmaf(v, w.x, acc.x);
        acc.y = fmaf(v, w.y, acc.y);
        acc.z = fmaf(v, w.z, acc.z);
        acc.w = fmaf(v, w.w, acc.w);
    }
    *(float4*)(recon + (size_t)row * ND + d) = acc;
}

// ---------------- launch ----------------
extern "C" void kernel_launch(void* const* d_in, const int* in_sizes, int n_in,
                              void* d_out, int out_size) {
    const float* x     = (const float*)d_in[0];
    const float* enc_w = (const float*)d_in[1];
    const float* enc_b = (const float*)d_in[2];
    const float* dec_w = (const float*)d_in[3];
    const float* dec_b = (const float*)d_in[4];

    float* recon  = (float*)d_out;                       // [B, D]
    float* sparse = (float*)d_out + (size_t)NB * ND;     // [B, F]

    cudaFuncSetAttribute(tc_gemm_kernel,
                         cudaFuncAttributeMaxDynamicSharedMemorySize, GEMM_SMEM);

    __half *a0, *b0;
    cudaGetSymbolAddress((void**)&a0, g_a0);
    cudaGetSymbolAddress((void**)&b0, g_b0);

    tof16_kernel<<<2048, 256>>>((const float4*)x, a0, NB * ND / 4);
    tof16_kernel<<<2048, 256>>>((const float4*)enc_w, b0, NF * ND / 4);

    compute_c_kernel<<<NF / 8, 256>>>(enc_w, enc_b, dec_b);
    transpose_kernel<<<dim3(NF / 32, ND / 32), dim3(32, 8)>>>(dec_w);

    tc_gemm_kernel<<<dim3(NF / 128, NB / 128), 256, GEMM_SMEM>>>(sparse);

    topk_kernel<<<NB, 256>>>();
    rerank_kernel<<<NB, 256>>>(x, enc_w, sparse);
    decode_kernel<<<NB, 256>>>(dec_b, recon);
}

// round 12
// speedup vs baseline: 1.0662x; 1.0662x over previous
#include <cuda_runtime.h>
#include <cuda_bf16.h>
#include <cuda_fp16.h>
#include <cstdint>

// Problem constants
#define NB   16384   // batch rows
#define ND   1024    // model dim
#define NF   8192    // features
#define KTOP 30
#define NCAND 40     // approx candidates kept per row (wide margin vs gap tails)

// ---------------- device scratch (no allocations allowed) ----------------
__device__ unsigned short g_preh[(size_t)NB * NF];  // approx scores, fp16 bits, 256 MB
__device__ __half g_dwt_h[(size_t)NF * ND]; // dec_w transposed [F, D], fp16, 16 MB (L2-resident)
__device__ float g_c[NF];                   // folded bias: enc_b - enc_w @ dec_b
__device__ int   g_cand[(size_t)NB * NCAND];// candidate indices (approx top-40)
__device__ float g_wv[(size_t)NB * 32];     // exact relu(top-30) values
__device__ int   g_wi[(size_t)NB * 32];     // exact top-30 indices
// bf16 copies
__device__ __nv_bfloat16 g_a0[(size_t)NB * ND];
__device__ __nv_bfloat16 g_b0[(size_t)NF * ND];

// ======================= PTX helpers (baseline sm_80+ features only) =======================
__device__ __forceinline__ uint32_t smem_to_u32(const void* smem_ptr) {
    uint32_t addr;
    asm("{ .reg .u64 tmp; cvta.to.shared.u64 tmp, %1; cvt.u32.u64 %0, tmp; }"
        : "=r"(addr) : "l"(smem_ptr));
    return addr;
}

__device__ __forceinline__ void cp_async16(uint32_t dst, const void* src) {
    asm volatile("cp.async.cg.shared.global [%0], [%1], 16;"
                 :: "r"(dst), "l"(src));
}
#define CP_COMMIT() asm volatile("cp.async.commit_group;" ::: "memory")
#define CP_WAIT(n)  asm volatile("cp.async.wait_group %0;" :: "n"(n) : "memory")

__device__ __forceinline__ void ldsm4(uint32_t r[4], uint32_t addr) {
    asm volatile("ldmatrix.sync.aligned.m8n8.x4.shared.b16 {%0,%1,%2,%3}, [%4];"
                 : "=r"(r[0]), "=r"(r[1]), "=r"(r[2]), "=r"(r[3]) : "r"(addr));
}

__device__ __forceinline__ void mma_bf16(float d[4], const uint32_t a[4],
                                         uint32_t b0, uint32_t b1) {
    asm volatile(
        "mma.sync.aligned.m16n8k16.row.col.f32.bf16.bf16.f32 "
        "{%0,%1,%2,%3}, {%4,%5,%6,%7}, {%8,%9}, {%0,%1,%2,%3};"
        : "+f"(d[0]), "+f"(d[1]), "+f"(d[2]), "+f"(d[3])
        : "r"(a[0]), "r"(a[1]), "r"(a[2]), "r"(a[3]), "r"(b0), "r"(b1));
}

// ---------------- fp32 -> bf16 convert ----------------
__global__ void tobf16_kernel(const float4* __restrict__ in,
                              __nv_bfloat16* __restrict__ o0, int n4) {
    int i   = blockIdx.x * blockDim.x + threadIdx.x;
    int str = gridDim.x * blockDim.x;
    for (; i < n4; i += str) {
        float4 v = in[i];
        uint2 u0;
        ((__nv_bfloat16*)&u0)[0] = __float2bfloat16(v.x);
        ((__nv_bfloat16*)&u0)[1] = __float2bfloat16(v.y);
        ((__nv_bfloat16*)&u0)[2] = __float2bfloat16(v.z);
        ((__nv_bfloat16*)&u0)[3] = __float2bfloat16(v.w);
        *(uint2*)(o0 + (size_t)4 * i) = u0;
    }
}

// ---------------- c[f] = enc_b[f] - sum_d enc_w[f,d] * dec_b[d] ----------------
__global__ void compute_c_kernel(const float* __restrict__ enc_w,
                                 const float* __restrict__ enc_b,
                                 const float* __restrict__ dec_b) {
    int f    = blockIdx.x * 8 + (threadIdx.x >> 5);
    int lane = threadIdx.x & 31;
    const float* wrow = enc_w + (size_t)f * ND;
    float s = 0.f;
    #pragma unroll 8
    for (int d = lane; d < ND; d += 32) s += wrow[d] * dec_b[d];
    #pragma unroll
    for (int off = 16; off; off >>= 1) s += __shfl_down_sync(0xffffffffu, s, off);
    if (lane == 0) g_c[f] = enc_b[f] - s;
}

// ---------------- transpose dec_w [D,F] -> g_dwt_h [F,D] (fp16) ----------------
__global__ void transpose_kernel(const float* __restrict__ dec_w) {
    __shared__ float tile[32][33];
    int f0 = blockIdx.x * 32, d0 = blockIdx.y * 32;
    int tx = threadIdx.x, ty = threadIdx.y;   // 32 x 8
    #pragma unroll
    for (int q = 0; q < 4; q++)
        tile[ty + q * 8][tx] = dec_w[(size_t)(d0 + ty + q * 8) * NF + f0 + tx];
    __syncthreads();
    #pragma unroll
    for (int q = 0; q < 4; q++)
        g_dwt_h[(size_t)(f0 + ty + q * 8) * ND + d0 + tx] =
            __float2half(tile[tx][ty + q * 8]);
}

// =====================================================================
// mma.sync bf16 GEMM (K=1024):  g_preh ~= f16(x @ enc_w^T + c)
// + zero-fill of the sparse output tile (free on DRAM headroom)
// CTA 128x128, 8 warps (2Mx4N, warp tile 64x32), BK=32, 4-stage cp.async
// =====================================================================
#define BKC    32
#define ROWB   80                    // smem row stride bytes (64 data + 16 pad)
#define ASTG   (128 * ROWB)          // 10240 bytes
#define STGB   (2 * ASTG)            // 20480 bytes per stage (A then B)
#define GEMM_SMEM (4 * STGB)         // 81920
#define NCHUNK (ND / BKC)            // 32

__device__ __forceinline__ void load_stage(uint32_t sm,
                                           const __nv_bfloat16* __restrict__ ga,
                                           const __nv_bfloat16* __restrict__ gb,
                                           int kbase, int tid) {
    #pragma unroll
    for (int h = 0; h < 2; h++) {
        int c = tid + h * 256;           // 0..511
        int row = c >> 2, kc = c & 3;
        cp_async16(sm + row * ROWB + kc * 16,
                   ga + (size_t)row * ND + kbase + kc * 8);
    }
    #pragma unroll
    for (int h = 0; h < 2; h++) {
        int c = tid + h * 256;
        int row = c >> 2, kc = c & 3;
        cp_async16(sm + ASTG + row * ROWB + kc * 16,
                   gb + (size_t)row * ND + kbase + kc * 8);
    }
}

__global__ __launch_bounds__(256)
void tc_gemm_kernel(float* __restrict__ sparse) {
    extern __shared__ __align__(128) char smem[];
    const uint32_t base = smem_to_u32(smem);
    const int tid  = threadIdx.x;
    const int lane = tid & 31;
    const int wid  = tid >> 5;
    const int wm   = wid >> 2;       // 0..1
    const int wn   = wid & 3;        // 0..3
    const int m0 = blockIdx.y * 128;
    const int n0 = blockIdx.x * 128;

    const __nv_bfloat16* AP = g_a0 + (size_t)m0 * ND;
    const __nv_bfloat16* BP = g_b0 + (size_t)n0 * ND;

    // prologue: stages 0..2
    #pragma unroll
    for (int q = 0; q < 3; q++) {
        load_stage(base + q * STGB, AP, BP, q * BKC, tid);
        CP_COMMIT();
    }

    // zero-fill this CTA's 128x128 sparse tile while loads are in flight
    {
        float4 z4 = make_float4(0.f, 0.f, 0.f, 0.f);
        float4* sp = (float4*)(sparse + (size_t)m0 * NF + n0);
        #pragma unroll
        for (int q = 0; q < 16; q++) {
            int u = q * 256 + tid;
            int r = u >> 5, sl = u & 31;      // 32 float4 slots per 128-col row
            sp[(size_t)r * (NF / 4) + sl] = z4;
        }
    }

    float acc[4][4][4] = {};

    // precomputed ldmatrix lane-address components
    const uint32_t a_row  = (uint32_t)(wm * 64 + (lane & 15)) * ROWB
                          + (uint32_t)(lane >> 4) * 16;
    const int g  = lane >> 3, r8 = lane & 7;
    const uint32_t b_row  = ASTG
        + (uint32_t)(wn * 32 + ((g >> 1) * 8) + r8) * ROWB
        + (uint32_t)(g & 1) * 16;

    for (int q = 0; q < NCHUNK; q++) {
        const uint32_t sb = base + (uint32_t)(q & 3) * STGB;
        CP_WAIT(2);
        __syncthreads();

        #pragma unroll
        for (int k16 = 0; k16 < 2; k16++) {
            uint32_t a[4][4], b[2][4];
            #pragma unroll
            for (int mi = 0; mi < 4; mi++)
                ldsm4(a[mi], sb + a_row + mi * 16 * ROWB + k16 * 32);
            #pragma unroll
            for (int nj = 0; nj < 2; nj++)
                ldsm4(b[nj], sb + b_row + nj * 16 * ROWB + k16 * 32);
            #pragma unroll
            for (int mi = 0; mi < 4; mi++) {
                #pragma unroll
                for (int nj = 0; nj < 2; nj++) {
                    mma_bf16(acc[mi][nj * 2 + 0], a[mi], b[nj][0], b[nj][1]);
                    mma_bf16(acc[mi][nj * 2 + 1], a[mi], b[nj][2], b[nj][3]);
                }
            }
        }

        if (q + 3 < NCHUNK) {
            int qq = q + 3;
            load_stage(base + (uint32_t)(qq & 3) * STGB, AP, BP, qq * BKC, tid);
        }
        CP_COMMIT();
    }

    // epilogue: acc + folded bias -> fp16 bits in g_preh
    const int lr = lane >> 2;
    const int lc = (lane & 3) * 2;
    #pragma unroll
    for (int j = 0; j < 4; j++) {
        const int col = n0 + wn * 32 + j * 8 + lc;
        const float cx = g_c[col], cy = g_c[col + 1];
        #pragma unroll
        for (int mi = 0; mi < 4; mi++) {
            const int r0 = m0 + wm * 64 + mi * 16 + lr;
            __half2 o0 = __floats2half2_rn(acc[mi][j][0] + cx, acc[mi][j][1] + cy);
            __half2 o1 = __floats2half2_rn(acc[mi][j][2] + cx, acc[mi][j][3] + cy);
            *(uint32_t*)&g_preh[(size_t)r0 * NF + col]       = *(uint32_t*)&o0;
            *(uint32_t*)&g_preh[(size_t)(r0 + 8) * NF + col] = *(uint32_t*)&o1;
        }
    }
}

// ---------------- approx top-40 per row (32-bit packed fp16 keys) ----------------
__global__ __launch_bounds__(256)
void topk_kernel() {
    const int row = blockIdx.x;
    const int tid = threadIdx.x;
    const uint4* pre = (const uint4*)(g_preh + (size_t)row * NF);

    // pack: (key16 << 13) | (8191 - gidx); key16 = order-preserving fp16 map
    uint32_t pk[32];
    #pragma unroll
    for (int v = 0; v < 4; v++) {
        uint4 u = pre[v * 256 + tid];
        uint32_t rr[4] = {u.x, u.y, u.z, u.w};
        #pragma unroll
        for (int p = 0; p < 4; p++) {
            uint32_t lo = rr[p] & 0xFFFFu, hi = rr[p] >> 16;
            lo = (lo & 0x8000u) ? (~lo & 0xFFFFu) : (lo | 0x8000u);
            hi = (hi & 0x8000u) ? (~hi & 0xFFFFu) : (hi | 0x8000u);
            uint32_t g0 = (uint32_t)(v * 2048 + tid * 8 + p * 2);
            pk[v * 8 + p * 2 + 0] = (lo << 13) | (8191u - g0);
            pk[v * 8 + p * 2 + 1] = (hi << 13) | (8191u - (g0 + 1));
        }
    }

    uint32_t live = 0xFFFFFFFFu;
    uint32_t best = 0;
    #pragma unroll
    for (int i = 0; i < 32; i++) best = max(best, pk[i]);

    __shared__ uint32_t swarp[8];
    __shared__ uint32_t swin;
    __shared__ int winI[NCAND];

    for (int t = 0; t < NCAND; t++) {
        uint32_t p = best;
        #pragma unroll
        for (int off = 16; off; off >>= 1)
            p = max(p, __shfl_down_sync(0xffffffffu, p, off));
        if ((tid & 31) == 0) swarp[tid >> 5] = p;
        __syncthreads();
        if (tid < 32) {
            uint32_t q = (tid < 8) ? swarp[tid] : 0u;
            #pragma unroll
            for (int off = 4; off; off >>= 1)
                q = max(q, __shfl_down_sync(0xffffffffu, q, off));
            if (tid == 0) swin = q;
        }
        __syncthreads();
        const uint32_t w = swin;
        const uint32_t gidx = 8191u - (w & 0x1FFFu);
        if (tid == (int)((gidx & 2047u) >> 3)) {
            const int slot = (int)((gidx >> 11) * 8 + (gidx & 7u));
            live &= ~(1u << slot);
            winI[t] = (int)gidx;
            best = 0;
            #pragma unroll
            for (int i = 0; i < 32; i++)
                if ((live >> i) & 1u) best = max(best, pk[i]);
        }
        __syncthreads();
    }

    if (tid < NCAND) g_cand[(size_t)row * NCAND + tid] = winI[tid];
}

// ---------------- exact fp32 rerank of 40 candidates -> top-30 ----------------
__global__ __launch_bounds__(256)
void rerank_kernel(const float* __restrict__ x,
                   const float* __restrict__ enc_w,
                   float* __restrict__ sparse) {
    __shared__ float4 xs[ND / 4];
    __shared__ float  sc[NCAND];
    __shared__ int    si[NCAND];
    __shared__ int    cnt;
    const int row = blockIdx.x;
    const int tid = threadIdx.x;
    const int wid = tid >> 5, lane = tid & 31;

    xs[tid] = ((const float4*)(x + (size_t)row * ND))[tid];
    if (tid == 0) cnt = 0;
    __syncthreads();

    #pragma unroll
    for (int cc = 0; cc < NCAND / 8; cc++) {
        const int c = wid * (NCAND / 8) + cc;
        const int f = g_cand[(size_t)row * NCAND + c];
        const float4* wr = (const float4*)(enc_w + (size_t)f * ND);
        float s = 0.f;
        #pragma unroll
        for (int j = lane; j < ND / 4; j += 32) {
            float4 wv = wr[j], xv = xs[j];
            s += wv.x * xv.x + wv.y * xv.y + wv.z * xv.z + wv.w * xv.w;
        }
        #pragma unroll
        for (int off = 16; off; off >>= 1) s += __shfl_down_sync(0xffffffffu, s, off);
        if (lane == 0) { sc[c] = s + g_c[f]; si[c] = f; }
    }
    __syncthreads();

    if (tid < NCAND) {
        const float v = sc[tid];
        const int   f = si[tid];
        int rank = 0;
        #pragma unroll
        for (int j = 0; j < NCAND; j++)
            rank += (sc[j] > v) || (sc[j] == v && si[j] < f);
        if (rank < KTOP) {
            const float rv = fmaxf(v, 0.f);
            sparse[(size_t)row * NF + f] = rv;
            int slot = atomicAdd(&cnt, 1);
            g_wv[(size_t)row * 32 + slot] = rv;
            g_wi[(size_t)row * 32 + slot] = f;
        }
    }
}

// ---------------- decode: recon[row,:] = dec_b + sum_k v_k * dec_wT_h[idx_k,:] ----------------
__global__ __launch_bounds__(256)
void decode_kernel(const float* __restrict__ dec_b, float* __restrict__ recon) {
    __shared__ float sv[KTOP];
    __shared__ int   si[KTOP];
    const int row = blockIdx.x;
    const int tid = threadIdx.x;
    if (tid < KTOP) {
        sv[tid] = g_wv[(size_t)row * 32 + tid];
        si[tid] = g_wi[(size_t)row * 32 + tid];
    }
    __syncthreads();

    const int d = tid * 4;
    float4 acc = *(const float4*)(dec_b + d);
    #pragma unroll 5
    for (int k = 0; k < KTOP; k++) {
        const float v = sv[k];
        const uint2 u = *(const uint2*)(g_dwt_h + (size_t)si[k] * ND + d);
        const float2 w0 = __half22float2(*(const __half2*)&u.x);
        const float2 w1 = __half22float2(*(const __half2*)&u.y);
        acc.x = fmaf(v, w0.x, acc.x);
        acc.y = fmaf(v, w0.y, acc.y);
        acc.z = fmaf(v, w1.x, acc.z);
        acc.w = fmaf(v, w1.y, acc.w);
    }
    *(float4*)(recon + (size_t)row * ND + d) = acc;
}

// ---------------- launch ----------------
extern "C" void kernel_launch(void* const* d_in, const int* in_sizes, int n_in,
                              void* d_out, int out_size) {
    const float* x     = (const float*)d_in[0];
    const float* enc_w = (const float*)d_in[1];
    const float* enc_b = (const float*)d_in[2];
    const float* dec_w = (const float*)d_in[3];
    const float* dec_b = (const float*)d_in[4];

    float* recon  = (float*)d_out;                       // [B, D]
    float* sparse = (float*)d_out + (size_t)NB * ND;     // [B, F]

    cudaFuncSetAttribute(tc_gemm_kernel,
                         cudaFuncAttributeMaxDynamicSharedMemorySize, GEMM_SMEM);

    __nv_bfloat16 *a0, *b0;
    cudaGetSymbolAddress((void**)&a0, g_a0);
    cudaGetSymbolAddress((void**)&b0, g_b0);

    tobf16_kernel<<<2048, 256>>>((const float4*)x, a0, NB * ND / 4);
    tobf16_kernel<<<2048, 256>>>((const float4*)enc_w, b0, NF * ND / 4);

    compute_c_kernel<<<NF / 8, 256>>>(enc_w, enc_b, dec_b);
    transpose_kernel<<<dim3(NF / 32, ND / 32), dim3(32, 8)>>>(dec_w);

    tc_gemm_kernel<<<dim3(NF / 128, NB / 128), 256, GEMM_SMEM>>>(sparse);

    topk_kernel<<<NB, 256>>>();
    rerank_kernel<<<NB, 256>>>(x, enc_w, sparse);
    decode_kernel<<<NB, 256>>>(dec_b, recon);
}

// round 13
// speedup vs baseline: 1.0710x; 1.0045x over previous
#include <cuda_runtime.h>
#include <cuda_bf16.h>
#include <cuda_fp16.h>
#include <cstdint>

// Problem constants
#define NB   16384   // batch rows
#define ND   1024    // model dim
#define NF   8192    // features
#define KTOP 30
#define NCAND 36     // approx candidates kept per row (35-sigma margin)

// ---------------- device scratch (no allocations allowed) ----------------
__device__ unsigned short g_preh[(size_t)NB * NF];  // approx scores, fp16 bits, 256 MB
__device__ __half g_dwt_h[(size_t)NF * ND]; // dec_w transposed [F, D], fp16, 16 MB (L2-resident)
__device__ float g_c[NF];                   // folded bias: enc_b - enc_w @ dec_b
__device__ int   g_cand[(size_t)NB * NCAND];// candidate indices (approx top-36)
__device__ float g_wv[(size_t)NB * 32];     // exact relu(top-30) values
__device__ int   g_wi[(size_t)NB * 32];     // exact top-30 indices
// bf16 copies
__device__ __nv_bfloat16 g_a0[(size_t)NB * ND];
__device__ __nv_bfloat16 g_b0[(size_t)NF * ND];

// ======================= PTX helpers (baseline sm_80+ features only) =======================
__device__ __forceinline__ uint32_t smem_to_u32(const void* smem_ptr) {
    uint32_t addr;
    asm("{ .reg .u64 tmp; cvta.to.shared.u64 tmp, %1; cvt.u32.u64 %0, tmp; }"
        : "=r"(addr) : "l"(smem_ptr));
    return addr;
}

__device__ __forceinline__ void cp_async16(uint32_t dst, const void* src) {
    asm volatile("cp.async.cg.shared.global [%0], [%1], 16;"
                 :: "r"(dst), "l"(src));
}
#define CP_COMMIT() asm volatile("cp.async.commit_group;" ::: "memory")
#define CP_WAIT(n)  asm volatile("cp.async.wait_group %0;" :: "n"(n) : "memory")

__device__ __forceinline__ void ldsm4(uint32_t r[4], uint32_t addr) {
    asm volatile("ldmatrix.sync.aligned.m8n8.x4.shared.b16 {%0,%1,%2,%3}, [%4];"
                 : "=r"(r[0]), "=r"(r[1]), "=r"(r[2]), "=r"(r[3]) : "r"(addr));
}

__device__ __forceinline__ void mma_bf16(float d[4], const uint32_t a[4],
                                         uint32_t b0, uint32_t b1) {
    asm volatile(
        "mma.sync.aligned.m16n8k16.row.col.f32.bf16.bf16.f32 "
        "{%0,%1,%2,%3}, {%4,%5,%6,%7}, {%8,%9}, {%0,%1,%2,%3};"
        : "+f"(d[0]), "+f"(d[1]), "+f"(d[2]), "+f"(d[3])
        : "r"(a[0]), "r"(a[1]), "r"(a[2]), "r"(a[3]), "r"(b0), "r"(b1));
}

// ---------------- fp32 -> bf16 convert (x) ----------------
__global__ void tobf16_kernel(const float4* __restrict__ in,
                              __nv_bfloat16* __restrict__ o0, int n4) {
    int i   = blockIdx.x * blockDim.x + threadIdx.x;
    int str = gridDim.x * blockDim.x;
    for (; i < n4; i += str) {
        float4 v = in[i];
        uint2 u0;
        ((__nv_bfloat16*)&u0)[0] = __float2bfloat16(v.x);
        ((__nv_bfloat16*)&u0)[1] = __float2bfloat16(v.y);
        ((__nv_bfloat16*)&u0)[2] = __float2bfloat16(v.z);
        ((__nv_bfloat16*)&u0)[3] = __float2bfloat16(v.w);
        *(uint2*)(o0 + (size_t)4 * i) = u0;
    }
}

// ---------------- fused enc_w prep: bf16 convert + c[f] = enc_b[f] - enc_w[f,:]·dec_b ----------------
__global__ __launch_bounds__(256)
void prep_encw_kernel(const float4* __restrict__ enc_w4,
                      const float* __restrict__ enc_b,
                      const float* __restrict__ dec_b,
                      __nv_bfloat16* __restrict__ b0out) {
    __shared__ float4 db[ND / 4];
    const int tid = threadIdx.x;
    const int wid = tid >> 5, lane = tid & 31;
    db[tid] = ((const float4*)dec_b)[tid];
    __syncthreads();

    const int f = blockIdx.x * 8 + wid;
    const float4* row = enc_w4 + (size_t)f * (ND / 4);
    __nv_bfloat16* out = b0out + (size_t)f * ND;
    float s = 0.f;
    #pragma unroll
    for (int k = 0; k < 8; k++) {
        const int j = lane + k * 32;
        float4 w = row[j];
        float4 d = db[j];
        s += w.x * d.x + w.y * d.y + w.z * d.z + w.w * d.w;
        uint2 u;
        ((__nv_bfloat16*)&u)[0] = __float2bfloat16(w.x);
        ((__nv_bfloat16*)&u)[1] = __float2bfloat16(w.y);
        ((__nv_bfloat16*)&u)[2] = __float2bfloat16(w.z);
        ((__nv_bfloat16*)&u)[3] = __float2bfloat16(w.w);
        *(uint2*)(out + j * 4) = u;
    }
    #pragma unroll
    for (int off = 16; off; off >>= 1) s += __shfl_down_sync(0xffffffffu, s, off);
    if (lane == 0) g_c[f] = enc_b[f] - s;
}

// ---------------- transpose dec_w [D,F] -> g_dwt_h [F,D] (fp16) ----------------
__global__ void transpose_kernel(const float* __restrict__ dec_w) {
    __shared__ float tile[32][33];
    int f0 = blockIdx.x * 32, d0 = blockIdx.y * 32;
    int tx = threadIdx.x, ty = threadIdx.y;   // 32 x 8
    #pragma unroll
    for (int q = 0; q < 4; q++)
        tile[ty + q * 8][tx] = dec_w[(size_t)(d0 + ty + q * 8) * NF + f0 + tx];
    __syncthreads();
    #pragma unroll
    for (int q = 0; q < 4; q++)
        g_dwt_h[(size_t)(f0 + ty + q * 8) * ND + d0 + tx] =
            __float2half(tile[tx][ty + q * 8]);
}

// =====================================================================
// mma.sync bf16 GEMM (K=1024):  g_preh ~= f16(x @ enc_w^T + c)
// + zero-fill of the sparse output tile (free on DRAM headroom)
// CTA 128x128, 8 warps (2Mx4N, warp tile 64x32), BK=32, 4-stage cp.async
// =====================================================================
#define BKC    32
#define ROWB   80                    // smem row stride bytes (64 data + 16 pad)
#define ASTG   (128 * ROWB)          // 10240 bytes
#define STGB   (2 * ASTG)            // 20480 bytes per stage (A then B)
#define GEMM_SMEM (4 * STGB)         // 81920
#define NCHUNK (ND / BKC)            // 32

__device__ __forceinline__ void load_stage(uint32_t sm,
                                           const __nv_bfloat16* __restrict__ ga,
                                           const __nv_bfloat16* __restrict__ gb,
                                           int kbase, int tid) {
    #pragma unroll
    for (int h = 0; h < 2; h++) {
        int c = tid + h * 256;           // 0..511
        int row = c >> 2, kc = c & 3;
        cp_async16(sm + row * ROWB + kc * 16,
                   ga + (size_t)row * ND + kbase + kc * 8);
    }
    #pragma unroll
    for (int h = 0; h < 2; h++) {
        int c = tid + h * 256;
        int row = c >> 2, kc = c & 3;
        cp_async16(sm + ASTG + row * ROWB + kc * 16,
                   gb + (size_t)row * ND + kbase + kc * 8);
    }
}

__global__ __launch_bounds__(256)
void tc_gemm_kernel(float* __restrict__ sparse) {
    extern __shared__ __align__(128) char smem[];
    const uint32_t base = smem_to_u32(smem);
    const int tid  = threadIdx.x;
    const int lane = tid & 31;
    const int wid  = tid >> 5;
    const int wm   = wid >> 2;       // 0..1
    const int wn   = wid & 3;        // 0..3
    const int m0 = blockIdx.y * 128;
    const int n0 = blockIdx.x * 128;

    const __nv_bfloat16* AP = g_a0 + (size_t)m0 * ND;
    const __nv_bfloat16* BP = g_b0 + (size_t)n0 * ND;

    // prologue: stages 0..2
    #pragma unroll
    for (int q = 0; q < 3; q++) {
        load_stage(base + q * STGB, AP, BP, q * BKC, tid);
        CP_COMMIT();
    }

    // zero-fill this CTA's 128x128 sparse tile while loads are in flight
    {
        float4 z4 = make_float4(0.f, 0.f, 0.f, 0.f);
        float4* sp = (float4*)(sparse + (size_t)m0 * NF + n0);
        #pragma unroll
        for (int q = 0; q < 16; q++) {
            int u = q * 256 + tid;
            int r = u >> 5, sl = u & 31;      // 32 float4 slots per 128-col row
            sp[(size_t)r * (NF / 4) + sl] = z4;
        }
    }

    float acc[4][4][4] = {};

    // precomputed ldmatrix lane-address components
    const uint32_t a_row  = (uint32_t)(wm * 64 + (lane & 15)) * ROWB
                          + (uint32_t)(lane >> 4) * 16;
    const int g  = lane >> 3, r8 = lane & 7;
    const uint32_t b_row  = ASTG
        + (uint32_t)(wn * 32 + ((g >> 1) * 8) + r8) * ROWB
        + (uint32_t)(g & 1) * 16;

    for (int q = 0; q < NCHUNK; q++) {
        const uint32_t sb = base + (uint32_t)(q & 3) * STGB;
        CP_WAIT(2);
        __syncthreads();

        #pragma unroll
        for (int k16 = 0; k16 < 2; k16++) {
            uint32_t a[4][4], b[2][4];
            #pragma unroll
            for (int mi = 0; mi < 4; mi++)
                ldsm4(a[mi], sb + a_row + mi * 16 * ROWB + k16 * 32);
            #pragma unroll
            for (int nj = 0; nj < 2; nj++)
                ldsm4(b[nj], sb + b_row + nj * 16 * ROWB + k16 * 32);
            #pragma unroll
            for (int mi = 0; mi < 4; mi++) {
                #pragma unroll
                for (int nj = 0; nj < 2; nj++) {
                    mma_bf16(acc[mi][nj * 2 + 0], a[mi], b[nj][0], b[nj][1]);
                    mma_bf16(acc[mi][nj * 2 + 1], a[mi], b[nj][2], b[nj][3]);
                }
            }
        }

        if (q + 3 < NCHUNK) {
            int qq = q + 3;
            load_stage(base + (uint32_t)(qq & 3) * STGB, AP, BP, qq * BKC, tid);
        }
        CP_COMMIT();
    }

    // epilogue: acc + folded bias -> fp16 bits in g_preh
    const int lr = lane >> 2;
    const int lc = (lane & 3) * 2;
    #pragma unroll
    for (int j = 0; j < 4; j++) {
        const int col = n0 + wn * 32 + j * 8 + lc;
        const float cx = g_c[col], cy = g_c[col + 1];
        #pragma unroll
        for (int mi = 0; mi < 4; mi++) {
            const int r0 = m0 + wm * 64 + mi * 16 + lr;
            __half2 o0 = __floats2half2_rn(acc[mi][j][0] + cx, acc[mi][j][1] + cy);
            __half2 o1 = __floats2half2_rn(acc[mi][j][2] + cx, acc[mi][j][3] + cy);
            *(uint32_t*)&g_preh[(size_t)r0 * NF + col]       = *(uint32_t*)&o0;
            *(uint32_t*)&g_preh[(size_t)(r0 + 8) * NF + col] = *(uint32_t*)&o1;
        }
    }
}

// ---------------- approx top-36 per row (32-bit packed fp16 keys) ----------------
__global__ __launch_bounds__(256)
void topk_kernel() {
    const int row = blockIdx.x;
    const int tid = threadIdx.x;
    const uint4* pre = (const uint4*)(g_preh + (size_t)row * NF);

    // pack: (key16 << 13) | (8191 - gidx); key16 = order-preserving fp16 map
    uint32_t pk[32];
    #pragma unroll
    for (int v = 0; v < 4; v++) {
        uint4 u = pre[v * 256 + tid];
        uint32_t rr[4] = {u.x, u.y, u.z, u.w};
        #pragma unroll
        for (int p = 0; p < 4; p++) {
            uint32_t lo = rr[p] & 0xFFFFu, hi = rr[p] >> 16;
            lo = (lo & 0x8000u) ? (~lo & 0xFFFFu) : (lo | 0x8000u);
            hi = (hi & 0x8000u) ? (~hi & 0xFFFFu) : (hi | 0x8000u);
            uint32_t g0 = (uint32_t)(v * 2048 + tid * 8 + p * 2);
            pk[v * 8 + p * 2 + 0] = (lo << 13) | (8191u - g0);
            pk[v * 8 + p * 2 + 1] = (hi << 13) | (8191u - (g0 + 1));
        }
    }

    uint32_t live = 0xFFFFFFFFu;
    uint32_t best = 0;
    #pragma unroll
    for (int i = 0; i < 32; i++) best = max(best, pk[i]);

    __shared__ uint32_t swarp[8];
    __shared__ uint32_t swin;
    __shared__ int winI[NCAND];

    for (int t = 0; t < NCAND; t++) {
        uint32_t p = best;
        #pragma unroll
        for (int off = 16; off; off >>= 1)
            p = max(p, __shfl_down_sync(0xffffffffu, p, off));
        if ((tid & 31) == 0) swarp[tid >> 5] = p;
        __syncthreads();
        if (tid < 32) {
            uint32_t q = (tid < 8) ? swarp[tid] : 0u;
            #pragma unroll
            for (int off = 4; off; off >>= 1)
                q = max(q, __shfl_down_sync(0xffffffffu, q, off));
            if (tid == 0) swin = q;
        }
        __syncthreads();
        const uint32_t w = swin;
        const uint32_t gidx = 8191u - (w & 0x1FFFu);
        if (tid == (int)((gidx & 2047u) >> 3)) {
            const int slot = (int)((gidx >> 11) * 8 + (gidx & 7u));
            live &= ~(1u << slot);
            winI[t] = (int)gidx;
            best = 0;
            #pragma unroll
            for (int i = 0; i < 32; i++)
                if ((live >> i) & 1u) best = max(best, pk[i]);
        }
        __syncthreads();
    }

    if (tid < NCAND) g_cand[(size_t)row * NCAND + tid] = winI[tid];
}

// ---------------- exact fp32 rerank of 36 candidates -> top-30 ----------------
__global__ __launch_bounds__(256)
void rerank_kernel(const float* __restrict__ x,
                   const float* __restrict__ enc_w,
                   float* __restrict__ sparse) {
    __shared__ float4 xs[ND / 4];
    __shared__ float  sc[NCAND];
    __shared__ int    si[NCAND];
    __shared__ int    cnt;
    const int row = blockIdx.x;
    const int tid = threadIdx.x;
    const int wid = tid >> 5, lane = tid & 31;

    xs[tid] = ((const float4*)(x + (size_t)row * ND))[tid];
    if (tid == 0) cnt = 0;
    __syncthreads();

    for (int c = wid; c < NCAND; c += 8) {
        const int f = g_cand[(size_t)row * NCAND + c];
        const float4* wr = (const float4*)(enc_w + (size_t)f * ND);
        float s = 0.f;
        #pragma unroll
        for (int j = lane; j < ND / 4; j += 32) {
            float4 wv = wr[j], xv = xs[j];
            s += wv.x * xv.x + wv.y * xv.y + wv.z * xv.z + wv.w * xv.w;
        }
        #pragma unroll
        for (int off = 16; off; off >>= 1) s += __shfl_down_sync(0xffffffffu, s, off);
        if (lane == 0) { sc[c] = s + g_c[f]; si[c] = f; }
    }
    __syncthreads();

    if (tid < NCAND) {
        const float v = sc[tid];
        const int   f = si[tid];
        int rank = 0;
        #pragma unroll
        for (int j = 0; j < NCAND; j++)
            rank += (sc[j] > v) || (sc[j] == v && si[j] < f);
        if (rank < KTOP) {
            const float rv = fmaxf(v, 0.f);
            sparse[(size_t)row * NF + f] = rv;
            int slot = atomicAdd(&cnt, 1);
            g_wv[(size_t)row * 32 + slot] = rv;
            g_wi[(size_t)row * 32 + slot] = f;
        }
    }
}

// ---------------- decode: recon[row,:] = dec_b + sum_k v_k * dec_wT_h[idx_k,:] ----------------
__global__ __launch_bounds__(256)
void decode_kernel(const float* __restrict__ dec_b, float* __restrict__ recon) {
    __shared__ float sv[KTOP];
    __shared__ int   si[KTOP];
    const int row = blockIdx.x;
    const int tid = threadIdx.x;
    if (tid < KTOP) {
        sv[tid] = g_wv[(size_t)row * 32 + tid];
        si[tid] = g_wi[(size_t)row * 32 + tid];
    }
    __syncthreads();

    const int d = tid * 4;
    float4 acc = *(const float4*)(dec_b + d);
    #pragma unroll 5
    for (int k = 0; k < KTOP; k++) {
        const float v = sv[k];
        const uint2 u = *(const uint2*)(g_dwt_h + (size_t)si[k] * ND + d);
        const float2 w0 = __half22float2(*(const __half2*)&u.x);
        const float2 w1 = __half22float2(*(const __half2*)&u.y);
        acc.x = fmaf(v, w0.x, acc.x);
        acc.y = fmaf(v, w0.y, acc.y);
        acc.z = fmaf(v, w1.x, acc.z);
        acc.w = fmaf(v, w1.y, acc.w);
    }
    *(float4*)(recon + (size_t)row * ND + d) = acc;
}

// ---------------- launch ----------------
extern "C" void kernel_launch(void* const* d_in, const int* in_sizes, int n_in,
                              void* d_out, int out_size) {
    const float* x     = (const float*)d_in[0];
    const float* enc_w = (const float*)d_in[1];
    const float* enc_b = (const float*)d_in[2];
    const float* dec_w = (const float*)d_in[3];
    const float* dec_b = (const float*)d_in[4];

    float* recon  = (float*)d_out;                       // [B, D]
    float* sparse = (float*)d_out + (size_t)NB * ND;     // [B, F]

    cudaFuncSetAttribute(tc_gemm_kernel,
                         cudaFuncAttributeMaxDynamicSharedMemorySize, GEMM_SMEM);

    __nv_bfloat16 *a0, *b0;
    cudaGetSymbolAddress((void**)&a0, g_a0);
    cudaGetSymbolAddress((void**)&b0, g_b0);

    tobf16_kernel<<<2048, 256>>>((const float4*)x, a0, NB * ND / 4);
    prep_encw_kernel<<<NF / 8, 256>>>((const float4*)enc_w, enc_b, dec_b, b0);
    transpose_kernel<<<dim3(NF / 32, ND / 32), dim3(32, 8)>>>(dec_w);

    tc_gemm_kernel<<<dim3(NF / 128, NB / 128), 256, GEMM_SMEM>>>(sparse);

    topk_kernel<<<NB, 256>>>();
    rerank_kernel<<<NB, 256>>>(x, enc_w, sparse);
    decode_kernel<<<NB, 256>>>(dec_b, recon);
}

// round 14
// speedup vs baseline: 1.0736x; 1.0024x over previous
#include <cuda_runtime.h>
#include <cuda_bf16.h>
#include <cuda_fp16.h>
#include <cstdint>

// Problem constants
#define NB   16384   // batch rows
#define ND   1024    // model dim
#define NF   8192    // features
#define KTOP 30
#define NCAND 36     // approx candidates kept per row (35-sigma margin)

// ---------------- device scratch (no allocations allowed) ----------------
__device__ unsigned short g_preh[(size_t)NB * NF];  // approx scores, fp16 bits, 256 MB
__device__ __half g_dwt_h[(size_t)NF * ND]; // dec_w transposed [F, D], fp16, 16 MB (L2-resident)
__device__ float g_c[NF];                   // folded bias: enc_b - enc_w @ dec_b
__device__ int   g_cand[(size_t)NB * NCAND];// candidate indices (approx top-36)
__device__ float g_wv[(size_t)NB * 32];     // exact relu(top-30) values
__device__ int   g_wi[(size_t)NB * 32];     // exact top-30 indices
// bf16 copies
__device__ __nv_bfloat16 g_a0[(size_t)NB * ND];
__device__ __nv_bfloat16 g_b0[(size_t)NF * ND];

// ======================= PTX helpers (baseline sm_80+ features only) =======================
__device__ __forceinline__ uint32_t smem_to_u32(const void* smem_ptr) {
    uint32_t addr;
    asm("{ .reg .u64 tmp; cvta.to.shared.u64 tmp, %1; cvt.u32.u64 %0, tmp; }"
        : "=r"(addr) : "l"(smem_ptr));
    return addr;
}

__device__ __forceinline__ void cp_async16(uint32_t dst, const void* src) {
    asm volatile("cp.async.cg.shared.global [%0], [%1], 16;"
                 :: "r"(dst), "l"(src));
}
#define CP_COMMIT() asm volatile("cp.async.commit_group;" ::: "memory")
#define CP_WAIT(n)  asm volatile("cp.async.wait_group %0;" :: "n"(n) : "memory")

__device__ __forceinline__ void ldsm4(uint32_t r[4], uint32_t addr) {
    asm volatile("ldmatrix.sync.aligned.m8n8.x4.shared.b16 {%0,%1,%2,%3}, [%4];"
                 : "=r"(r[0]), "=r"(r[1]), "=r"(r[2]), "=r"(r[3]) : "r"(addr));
}

__device__ __forceinline__ void mma_bf16(float d[4], const uint32_t a[4],
                                         uint32_t b0, uint32_t b1) {
    asm volatile(
        "mma.sync.aligned.m16n8k16.row.col.f32.bf16.bf16.f32 "
        "{%0,%1,%2,%3}, {%4,%5,%6,%7}, {%8,%9}, {%0,%1,%2,%3};"
        : "+f"(d[0]), "+f"(d[1]), "+f"(d[2]), "+f"(d[3])
        : "r"(a[0]), "r"(a[1]), "r"(a[2]), "r"(a[3]), "r"(b0), "r"(b1));
}

// ---------------- fp32 -> bf16 convert (x) ----------------
__global__ void tobf16_kernel(const float4* __restrict__ in,
                              __nv_bfloat16* __restrict__ o0, int n4) {
    int i   = blockIdx.x * blockDim.x + threadIdx.x;
    int str = gridDim.x * blockDim.x;
    for (; i < n4; i += str) {
        float4 v = in[i];
        uint2 u0;
        ((__nv_bfloat16*)&u0)[0] = __float2bfloat16(v.x);
        ((__nv_bfloat16*)&u0)[1] = __float2bfloat16(v.y);
        ((__nv_bfloat16*)&u0)[2] = __float2bfloat16(v.z);
        ((__nv_bfloat16*)&u0)[3] = __float2bfloat16(v.w);
        *(uint2*)(o0 + (size_t)4 * i) = u0;
    }
}

// ---------------- fused enc_w prep: bf16 convert + c[f] = enc_b[f] - enc_w[f,:]·dec_b ----------------
__global__ __launch_bounds__(256)
void prep_encw_kernel(const float4* __restrict__ enc_w4,
                      const float* __restrict__ enc_b,
                      const float* __restrict__ dec_b,
                      __nv_bfloat16* __restrict__ b0out) {
    __shared__ float4 db[ND / 4];
    const int tid = threadIdx.x;
    const int wid = tid >> 5, lane = tid & 31;
    db[tid] = ((const float4*)dec_b)[tid];
    __syncthreads();

    const int f = blockIdx.x * 8 + wid;
    const float4* row = enc_w4 + (size_t)f * (ND / 4);
    __nv_bfloat16* out = b0out + (size_t)f * ND;
    float s = 0.f;
    #pragma unroll
    for (int k = 0; k < 8; k++) {
        const int j = lane + k * 32;
        float4 w = row[j];
        float4 d = db[j];
        s += w.x * d.x + w.y * d.y + w.z * d.z + w.w * d.w;
        uint2 u;
        ((__nv_bfloat16*)&u)[0] = __float2bfloat16(w.x);
        ((__nv_bfloat16*)&u)[1] = __float2bfloat16(w.y);
        ((__nv_bfloat16*)&u)[2] = __float2bfloat16(w.z);
        ((__nv_bfloat16*)&u)[3] = __float2bfloat16(w.w);
        *(uint2*)(out + j * 4) = u;
    }
    #pragma unroll
    for (int off = 16; off; off >>= 1) s += __shfl_down_sync(0xffffffffu, s, off);
    if (lane == 0) g_c[f] = enc_b[f] - s;
}

// ---------------- transpose dec_w [D,F] -> g_dwt_h [F,D] (fp16) ----------------
__global__ void transpose_kernel(const float* __restrict__ dec_w) {
    __shared__ float tile[32][33];
    int f0 = blockIdx.x * 32, d0 = blockIdx.y * 32;
    int tx = threadIdx.x, ty = threadIdx.y;   // 32 x 8
    #pragma unroll
    for (int q = 0; q < 4; q++)
        tile[ty + q * 8][tx] = dec_w[(size_t)(d0 + ty + q * 8) * NF + f0 + tx];
    __syncthreads();
    #pragma unroll
    for (int q = 0; q < 4; q++)
        g_dwt_h[(size_t)(f0 + ty + q * 8) * ND + d0 + tx] =
            __float2half(tile[tx][ty + q * 8]);
}

// =====================================================================
// mma.sync bf16 GEMM (K=1024):  g_preh ~= f16(x @ enc_w^T + c)
// + zero-fill of the sparse output tile (free on DRAM headroom)
// CTA 128x128, 8 warps (2Mx4N, warp tile 64x32)
// BK=64 (16 chunks, half the barriers), 3-stage cp.async, loads lead compute
// =====================================================================
#define BKC    64
#define ROWB   144                   // smem row stride bytes (128 data + 16 pad)
#define ASTG   (128 * ROWB)          // 18432 bytes
#define STGB   (2 * ASTG)            // 36864 bytes per stage (A then B)
#define NSTAGE 3
#define GEMM_SMEM (NSTAGE * STGB)    // 110592
#define NCHUNK (ND / BKC)            // 16

__device__ __forceinline__ void load_stage(uint32_t sm,
                                           const __nv_bfloat16* __restrict__ ga,
                                           const __nv_bfloat16* __restrict__ gb,
                                           int kbase, int tid) {
    #pragma unroll
    for (int h = 0; h < 4; h++) {
        int c = tid + h * 256;           // 0..1023
        int row = c >> 3, kc = c & 7;
        cp_async16(sm + row * ROWB + kc * 16,
                   ga + (size_t)row * ND + kbase + kc * 8);
    }
    #pragma unroll
    for (int h = 0; h < 4; h++) {
        int c = tid + h * 256;
        int row = c >> 3, kc = c & 7;
        cp_async16(sm + ASTG + row * ROWB + kc * 16,
                   gb + (size_t)row * ND + kbase + kc * 8);
    }
}

__global__ __launch_bounds__(256)
void tc_gemm_kernel(float* __restrict__ sparse) {
    extern __shared__ __align__(128) char smem[];
    const uint32_t base = smem_to_u32(smem);
    const int tid  = threadIdx.x;
    const int lane = tid & 31;
    const int wid  = tid >> 5;
    const int wm   = wid >> 2;       // 0..1
    const int wn   = wid & 3;        // 0..3
    const int m0 = blockIdx.y * 128;
    const int n0 = blockIdx.x * 128;

    const __nv_bfloat16* AP = g_a0 + (size_t)m0 * ND;
    const __nv_bfloat16* BP = g_b0 + (size_t)n0 * ND;

    // prologue: stages 0..1
    #pragma unroll
    for (int q = 0; q < 2; q++) {
        load_stage(base + q * STGB, AP, BP, q * BKC, tid);
        CP_COMMIT();
    }

    // zero-fill this CTA's 128x128 sparse tile while loads are in flight
    {
        float4 z4 = make_float4(0.f, 0.f, 0.f, 0.f);
        float4* sp = (float4*)(sparse + (size_t)m0 * NF + n0);
        #pragma unroll
        for (int q = 0; q < 16; q++) {
            int u = q * 256 + tid;
            int r = u >> 5, sl = u & 31;      // 32 float4 slots per 128-col row
            sp[(size_t)r * (NF / 4) + sl] = z4;
        }
    }

    float acc[4][4][4] = {};

    // precomputed ldmatrix lane-address components
    const uint32_t a_row  = (uint32_t)(wm * 64 + (lane & 15)) * ROWB
                          + (uint32_t)(lane >> 4) * 16;
    const int g  = lane >> 3, r8 = lane & 7;
    const uint32_t b_row  = ASTG
        + (uint32_t)(wn * 32 + ((g >> 1) * 8) + r8) * ROWB
        + (uint32_t)(g & 1) * 16;

    int sidx = 0;   // stage index of chunk q (mod 3)
    for (int q = 0; q < NCHUNK; q++) {
        const uint32_t sb = base + (uint32_t)sidx * STGB;
        CP_WAIT(1);
        __syncthreads();

        // issue next loads FIRST so DRAM/LSU work overlaps the HMMA block
        if (q + 2 < NCHUNK) {
            int nidx = sidx + 2; if (nidx >= NSTAGE) nidx -= NSTAGE;
            load_stage(base + (uint32_t)nidx * STGB, AP, BP, (q + 2) * BKC, tid);
        }
        CP_COMMIT();

        #pragma unroll
        for (int k16 = 0; k16 < 4; k16++) {
            uint32_t a[4][4], b[2][4];
            #pragma unroll
            for (int mi = 0; mi < 4; mi++)
                ldsm4(a[mi], sb + a_row + mi * 16 * ROWB + k16 * 32);
            #pragma unroll
            for (int nj = 0; nj < 2; nj++)
                ldsm4(b[nj], sb + b_row + nj * 16 * ROWB + k16 * 32);
            #pragma unroll
            for (int mi = 0; mi < 4; mi++) {
                #pragma unroll
                for (int nj = 0; nj < 2; nj++) {
                    mma_bf16(acc[mi][nj * 2 + 0], a[mi], b[nj][0], b[nj][1]);
                    mma_bf16(acc[mi][nj * 2 + 1], a[mi], b[nj][2], b[nj][3]);
                }
            }
        }

        if (++sidx == NSTAGE) sidx = 0;
    }

    // epilogue: acc + folded bias -> fp16 bits in g_preh
    const int lr = lane >> 2;
    const int lc = (lane & 3) * 2;
    #pragma unroll
    for (int j = 0; j < 4; j++) {
        const int col = n0 + wn * 32 + j * 8 + lc;
        const float cx = g_c[col], cy = g_c[col + 1];
        #pragma unroll
        for (int mi = 0; mi < 4; mi++) {
            const int r0 = m0 + wm * 64 + mi * 16 + lr;
            __half2 o0 = __floats2half2_rn(acc[mi][j][0] + cx, acc[mi][j][1] + cy);
            __half2 o1 = __floats2half2_rn(acc[mi][j][2] + cx, acc[mi][j][3] + cy);
            *(uint32_t*)&g_preh[(size_t)r0 * NF + col]       = *(uint32_t*)&o0;
            *(uint32_t*)&g_preh[(size_t)(r0 + 8) * NF + col] = *(uint32_t*)&o1;
        }
    }
}

// ---------------- approx top-36 per row (32-bit packed fp16 keys) ----------------
__global__ __launch_bounds__(256)
void topk_kernel() {
    const int row = blockIdx.x;
    const int tid = threadIdx.x;
    const uint4* pre = (const uint4*)(g_preh + (size_t)row * NF);

    // pack: (key16 << 13) | (8191 - gidx); key16 = order-preserving fp16 map
    uint32_t pk[32];
    #pragma unroll
    for (int v = 0; v < 4; v++) {
        uint4 u = pre[v * 256 + tid];
        uint32_t rr[4] = {u.x, u.y, u.z, u.w};
        #pragma unroll
        for (int p = 0; p < 4; p++) {
            uint32_t lo = rr[p] & 0xFFFFu, hi = rr[p] >> 16;
            lo = (lo & 0x8000u) ? (~lo & 0xFFFFu) : (lo | 0x8000u);
            hi = (hi & 0x8000u) ? (~hi & 0xFFFFu) : (hi | 0x8000u);
            uint32_t g0 = (uint32_t)(v * 2048 + tid * 8 + p * 2);
            pk[v * 8 + p * 2 + 0] = (lo << 13) | (8191u - g0);
            pk[v * 8 + p * 2 + 1] = (hi << 13) | (8191u - (g0 + 1));
        }
    }

    uint32_t live = 0xFFFFFFFFu;
    uint32_t best = 0;
    #pragma unroll
    for (int i = 0; i < 32; i++) best = max(best, pk[i]);

    __shared__ uint32_t swarp[8];
    __shared__ uint32_t swin;
    __shared__ int winI[NCAND];

    for (int t = 0; t < NCAND; t++) {
        uint32_t p = best;
        #pragma unroll
        for (int off = 16; off; off >>= 1)
            p = max(p, __shfl_down_sync(0xffffffffu, p, off));
        if ((tid & 31) == 0) swarp[tid >> 5] = p;
        __syncthreads();
        if (tid < 32) {
            uint32_t q = (tid < 8) ? swarp[tid] : 0u;
            #pragma unroll
            for (int off = 4; off; off >>= 1)
                q = max(q, __shfl_down_sync(0xffffffffu, q, off));
            if (tid == 0) swin = q;
        }
        __syncthreads();
        const uint32_t w = swin;
        const uint32_t gidx = 8191u - (w & 0x1FFFu);
        if (tid == (int)((gidx & 2047u) >> 3)) {
            const int slot = (int)((gidx >> 11) * 8 + (gidx & 7u));
            live &= ~(1u << slot);
            winI[t] = (int)gidx;
            best = 0;
            #pragma unroll
            for (int i = 0; i < 32; i++)
                if ((live >> i) & 1u) best = max(best, pk[i]);
        }
        __syncthreads();
    }

    if (tid < NCAND) g_cand[(size_t)row * NCAND + tid] = winI[tid];
}

// ---------------- exact fp32 rerank of 36 candidates -> top-30 ----------------
__global__ __launch_bounds__(256)
void rerank_kernel(const float* __restrict__ x,
                   const float* __restrict__ enc_w,
                   float* __restrict__ sparse) {
    __shared__ float4 xs[ND / 4];
    __shared__ float  sc[NCAND];
    __shared__ int    si[NCAND];
    __shared__ int    cnt;
    const int row = blockIdx.x;
    const int tid = threadIdx.x;
    const int wid = tid >> 5, lane = tid & 31;

    xs[tid] = ((const float4*)(x + (size_t)row * ND))[tid];
    if (tid == 0) cnt = 0;
    __syncthreads();

    for (int c = wid; c < NCAND; c += 8) {
        const int f = g_cand[(size_t)row * NCAND + c];
        const float4* wr = (const float4*)(enc_w + (size_t)f * ND);
        float s = 0.f;
        #pragma unroll
        for (int j = lane; j < ND / 4; j += 32) {
            float4 wv = wr[j], xv = xs[j];
            s += wv.x * xv.x + wv.y * xv.y + wv.z * xv.z + wv.w * xv.w;
        }
        #pragma unroll
        for (int off = 16; off; off >>= 1) s += __shfl_down_sync(0xffffffffu, s, off);
        if (lane == 0) { sc[c] = s + g_c[f]; si[c] = f; }
    }
    __syncthreads();

    if (tid < NCAND) {
        const float v = sc[tid];
        const int   f = si[tid];
        int rank = 0;
        #pragma unroll
        for (int j = 0; j < NCAND; j++)
            rank += (sc[j] > v) || (sc[j] == v && si[j] < f);
        if (rank < KTOP) {
            const float rv = fmaxf(v, 0.f);
            sparse[(size_t)row * NF + f] = rv;
            int slot = atomicAdd(&cnt, 1);
            g_wv[(size_t)row * 32 + slot] = rv;
            g_wi[(size_t)row * 32 + slot] = f;
        }
    }
}

// ---------------- decode: recon[row,:] = dec_b + sum_k v_k * dec_wT_h[idx_k,:] ----------------
__global__ __launch_bounds__(256)
void decode_kernel(const float* __restrict__ dec_b, float* __restrict__ recon) {
    __shared__ float sv[KTOP];
    __shared__ int   si[KTOP];
    const int row = blockIdx.x;
    const int tid = threadIdx.x;
    if (tid < KTOP) {
        sv[tid] = g_wv[(size_t)row * 32 + tid];
        si[tid] = g_wi[(size_t)row * 32 + tid];
    }
    __syncthreads();

    const int d = tid * 4;
    float4 acc = *(const float4*)(dec_b + d);
    #pragma unroll 5
    for (int k = 0; k < KTOP; k++) {
        const float v = sv[k];
        const uint2 u = *(const uint2*)(g_dwt_h + (size_t)si[k] * ND + d);
        const float2 w0 = __half22float2(*(const __half2*)&u.x);
        const float2 w1 = __half22float2(*(const __half2*)&u.y);
        acc.x = fmaf(v, w0.x, acc.x);
        acc.y = fmaf(v, w0.y, acc.y);
        acc.z = fmaf(v, w1.x, acc.z);
        acc.w = fmaf(v, w1.y, acc.w);
    }
    *(float4*)(recon + (size_t)row * ND + d) = acc;
}

// ---------------- launch ----------------
extern "C" void kernel_launch(void* const* d_in, const int* in_sizes, int n_in,
                              void* d_out, int out_size) {
    const float* x     = (const float*)d_in[0];
    const float* enc_w = (const float*)d_in[1];
    const float* enc_b = (const float*)d_in[2];
    const float* dec_w = (const float*)d_in[3];
    const float* dec_b = (const float*)d_in[4];

    float* recon  = (float*)d_out;                       // [B, D]
    float* sparse = (float*)d_out + (size_t)NB * ND;     // [B, F]

    cudaFuncSetAttribute(tc_gemm_kernel,
                         cudaFuncAttributeMaxDynamicSharedMemorySize, GEMM_SMEM);

    __nv_bfloat16 *a0, *b0;
    cudaGetSymbolAddress((void**)&a0, g_a0);
    cudaGetSymbolAddress((void**)&b0, g_b0);

    tobf16_kernel<<<2048, 256>>>((const float4*)x, a0, NB * ND / 4);
    prep_encw_kernel<<<NF / 8, 256>>>((const float4*)enc_w, enc_b, dec_b, b0);
    transpose_kernel<<<dim3(NF / 32, ND / 32), dim3(32, 8)>>>(dec_w);

    tc_gemm_kernel<<<dim3(NF / 128, NB / 128), 256, GEMM_SMEM>>>(sparse);

    topk_kernel<<<NB, 256>>>();
    rerank_kernel<<<NB, 256>>>(x, enc_w, sparse);
    decode_kernel<<<NB, 256>>>(dec_b, recon);
}

// round 16
// speedup vs baseline: 1.0947x; 1.0196x over previous
#include <cuda_runtime.h>
#include <cuda_bf16.h>
#include <cuda_fp16.h>
#include <cstdint>

// Problem constants
#define NB   16384   // batch rows
#define ND   1024    // model dim
#define NF   8192    // features
#define KTOP 30
#define NCAND 36     // approx candidates kept per row

// ---------------- device scratch (no allocations allowed) ----------------
__device__ uint32_t g_ckeys[(size_t)NB * 1024];  // per-row packed candidate keys (64 tiles x 16), 64 MB
__device__ __half g_dwt_h[(size_t)NF * ND]; // dec_w transposed [F, D], fp16, 16 MB (L2-resident)
__device__ float g_c[NF];                   // folded bias: enc_b - enc_w @ dec_b
__device__ int   g_cand[(size_t)NB * NCAND];// candidate indices (approx top-36)
__device__ float g_wv[(size_t)NB * 32];     // exact relu(top-30) values
__device__ int   g_wi[(size_t)NB * 32];     // exact top-30 indices
// bf16 copies
__device__ __nv_bfloat16 g_a0[(size_t)NB * ND];  // x, bf16 (GEMM)
__device__ __nv_bfloat16 g_b0[(size_t)NF * ND];  // enc_w, bf16 (GEMM)

// ======================= PTX helpers (baseline sm_80+ features only) =======================
__device__ __forceinline__ uint32_t smem_to_u32(const void* smem_ptr) {
    uint32_t addr;
    asm("{ .reg .u64 tmp; cvta.to.shared.u64 tmp, %1; cvt.u32.u64 %0, tmp; }"
        : "=r"(addr) : "l"(smem_ptr));
    return addr;
}

__device__ __forceinline__ void cp_async16(uint32_t dst, const void* src) {
    asm volatile("cp.async.cg.shared.global [%0], [%1], 16;"
                 :: "r"(dst), "l"(src));
}
#define CP_COMMIT() asm volatile("cp.async.commit_group;" ::: "memory")
#define CP_WAIT(n)  asm volatile("cp.async.wait_group %0;" :: "n"(n) : "memory")

__device__ __forceinline__ void ldsm4(uint32_t r[4], uint32_t addr) {
    asm volatile("ldmatrix.sync.aligned.m8n8.x4.shared.b16 {%0,%1,%2,%3}, [%4];"
                 : "=r"(r[0]), "=r"(r[1]), "=r"(r[2]), "=r"(r[3]) : "r"(addr));
}

__device__ __forceinline__ void mma_bf16(float d[4], const uint32_t a[4],
                                         uint32_t b0, uint32_t b1) {
    asm volatile(
        "mma.sync.aligned.m16n8k16.row.col.f32.bf16.bf16.f32 "
        "{%0,%1,%2,%3}, {%4,%5,%6,%7}, {%8,%9}, {%0,%1,%2,%3};"
        : "+f"(d[0]), "+f"(d[1]), "+f"(d[2]), "+f"(d[3])
        : "r"(a[0]), "r"(a[1]), "r"(a[2]), "r"(a[3]), "r"(b0), "r"(b1));
}

// ---------------- fp32 -> bf16 convert (x) ----------------
__global__ void tobf16_kernel(const float4* __restrict__ in,
                              __nv_bfloat16* __restrict__ o0, int n4) {
    int i   = blockIdx.x * blockDim.x + threadIdx.x;
    int str = gridDim.x * blockDim.x;
    for (; i < n4; i += str) {
        float4 v = in[i];
        uint2 u0;
        ((__nv_bfloat16*)&u0)[0] = __float2bfloat16(v.x);
        ((__nv_bfloat16*)&u0)[1] = __float2bfloat16(v.y);
        ((__nv_bfloat16*)&u0)[2] = __float2bfloat16(v.z);
        ((__nv_bfloat16*)&u0)[3] = __float2bfloat16(v.w);
        *(uint2*)(o0 + (size_t)4 * i) = u0;
    }
}

// ---------- fused enc_w prep: bf16 convert + c[f] = enc_b[f] - enc_w[f,:]·dec_b ----------
__global__ __launch_bounds__(256)
void prep_encw_kernel(const float4* __restrict__ enc_w4,
                      const float* __restrict__ enc_b,
                      const float* __restrict__ dec_b,
                      __nv_bfloat16* __restrict__ b0out) {
    __shared__ float4 db[ND / 4];
    const int tid = threadIdx.x;
    const int wid = tid >> 5, lane = tid & 31;
    db[tid] = ((const float4*)dec_b)[tid];
    __syncthreads();

    const int f = blockIdx.x * 8 + wid;
    const float4* row = enc_w4 + (size_t)f * (ND / 4);
    __nv_bfloat16* out = b0out + (size_t)f * ND;
    float s = 0.f;
    #pragma unroll
    for (int k = 0; k < 8; k++) {
        const int j = lane + k * 32;
        float4 w = row[j];
        float4 d = db[j];
        s += w.x * d.x + w.y * d.y + w.z * d.z + w.w * d.w;
        uint2 u;
        ((__nv_bfloat16*)&u)[0] = __float2bfloat16(w.x);
        ((__nv_bfloat16*)&u)[1] = __float2bfloat16(w.y);
        ((__nv_bfloat16*)&u)[2] = __float2bfloat16(w.z);
        ((__nv_bfloat16*)&u)[3] = __float2bfloat16(w.w);
        *(uint2*)(out + j * 4) = u;
    }
    #pragma unroll
    for (int off = 16; off; off >>= 1) s += __shfl_down_sync(0xffffffffu, s, off);
    if (lane == 0) g_c[f] = enc_b[f] - s;
}

// ---------------- transpose dec_w [D,F] -> g_dwt_h [F,D] (fp16) ----------------
__global__ void transpose_kernel(const float* __restrict__ dec_w) {
    __shared__ float tile[32][33];
    int f0 = blockIdx.x * 32, d0 = blockIdx.y * 32;
    int tx = threadIdx.x, ty = threadIdx.y;   // 32 x 8
    #pragma unroll
    for (int q = 0; q < 4; q++)
        tile[ty + q * 8][tx] = dec_w[(size_t)(d0 + ty + q * 8) * NF + f0 + tx];
    __syncthreads();
    #pragma unroll
    for (int q = 0; q < 4; q++)
        g_dwt_h[(size_t)(f0 + ty + q * 8) * ND + d0 + tx] =
            __float2half(tile[tx][ty + q * 8]);
}

// =====================================================================
// mma.sync bf16 GEMM (K=1024) with FUSED candidate selection:
// scores staged in smem; per-(row, 64-col half) top-8 packed keys written.
// CTA 128x128, 8 warps (2Mx4N, warp tile 64x32), BK=64, 3-stage cp.async
// =====================================================================
#define BKC    64
#define ROWB   144                   // smem row stride bytes (128 data + 16 pad)
#define ASTG   (128 * ROWB)          // 18432 bytes
#define STGB   (2 * ASTG)            // 36864 bytes per stage (A then B)
#define NSTAGE 3
#define GEMM_SMEM (NSTAGE * STGB)    // 110592
#define NCHUNK (ND / BKC)            // 16
#define SCSTR  136                   // score smem stride in halves (272 B, 16-aligned)

__device__ __forceinline__ void load_stage(uint32_t sm,
                                           const __nv_bfloat16* __restrict__ ga,
                                           const __nv_bfloat16* __restrict__ gb,
                                           int kbase, int tid) {
    #pragma unroll
    for (int h = 0; h < 4; h++) {
        int c = tid + h * 256;           // 0..1023
        int row = c >> 3, kc = c & 7;
        cp_async16(sm + row * ROWB + kc * 16,
                   ga + (size_t)row * ND + kbase + kc * 8);
    }
    #pragma unroll
    for (int h = 0; h < 4; h++) {
        int c = tid + h * 256;
        int row = c >> 3, kc = c & 7;
        cp_async16(sm + ASTG + row * ROWB + kc * 16,
                   gb + (size_t)row * ND + kbase + kc * 8);
    }
}

__global__ __launch_bounds__(256)
void tc_gemm_kernel(float* __restrict__ sparse) {
    extern __shared__ __align__(128) char smem[];
    const uint32_t base = smem_to_u32(smem);
    const int tid  = threadIdx.x;
    const int lane = tid & 31;
    const int wid  = tid >> 5;
    const int wm   = wid >> 2;       // 0..1
    const int wn   = wid & 3;        // 0..3
    const int m0 = blockIdx.y * 128;
    const int n0 = blockIdx.x * 128;

    const __nv_bfloat16* AP = g_a0 + (size_t)m0 * ND;
    const __nv_bfloat16* BP = g_b0 + (size_t)n0 * ND;

    // prologue: stages 0..1
    #pragma unroll
    for (int q = 0; q < 2; q++) {
        load_stage(base + q * STGB, AP, BP, q * BKC, tid);
        CP_COMMIT();
    }

    // zero-fill this CTA's 128x128 sparse tile while loads are in flight
    {
        float4 z4 = make_float4(0.f, 0.f, 0.f, 0.f);
        float4* sp = (float4*)(sparse + (size_t)m0 * NF + n0);
        #pragma unroll
        for (int q = 0; q < 16; q++) {
            int u = q * 256 + tid;
            int r = u >> 5, sl = u & 31;      // 32 float4 slots per 128-col row
            sp[(size_t)r * (NF / 4) + sl] = z4;
        }
    }

    float acc[4][4][4] = {};

    // precomputed ldmatrix lane-address components
    const uint32_t a_row  = (uint32_t)(wm * 64 + (lane & 15)) * ROWB
                          + (uint32_t)(lane >> 4) * 16;
    const int g  = lane >> 3, r8 = lane & 7;
    const uint32_t b_row  = ASTG
        + (uint32_t)(wn * 32 + ((g >> 1) * 8) + r8) * ROWB
        + (uint32_t)(g & 1) * 16;

    int sidx = 0;   // stage index of chunk q (mod 3)
    for (int q = 0; q < NCHUNK; q++) {
        const uint32_t sb = base + (uint32_t)sidx * STGB;
        CP_WAIT(1);
        __syncthreads();

        if (q + 2 < NCHUNK) {
            int nidx = sidx + 2; if (nidx >= NSTAGE) nidx -= NSTAGE;
            load_stage(base + (uint32_t)nidx * STGB, AP, BP, (q + 2) * BKC, tid);
        }
        CP_COMMIT();

        #pragma unroll
        for (int k16 = 0; k16 < 4; k16++) {
            uint32_t a[4][4], b[2][4];
            #pragma unroll
            for (int mi = 0; mi < 4; mi++)
                ldsm4(a[mi], sb + a_row + mi * 16 * ROWB + k16 * 32);
            #pragma unroll
            for (int nj = 0; nj < 2; nj++)
                ldsm4(b[nj], sb + b_row + nj * 16 * ROWB + k16 * 32);
            #pragma unroll
            for (int mi = 0; mi < 4; mi++) {
                #pragma unroll
                for (int nj = 0; nj < 2; nj++) {
                    mma_bf16(acc[mi][nj * 2 + 0], a[mi], b[nj][0], b[nj][1]);
                    mma_bf16(acc[mi][nj * 2 + 1], a[mi], b[nj][2], b[nj][3]);
                }
            }
        }

        if (++sidx == NSTAGE) sidx = 0;
    }

    // ---- fused epilogue: stage fp16 scores in smem, select per-half top-8 ----
    __syncthreads();   // all warps done reading pipeline smem
    unsigned short* sc = (unsigned short*)smem;
    {
        const int lr = lane >> 2;
        const int lc = (lane & 3) * 2;
        #pragma unroll
        for (int j = 0; j < 4; j++) {
            const int col = wn * 32 + j * 8 + lc;          // local col 0..127
            const float cx = g_c[n0 + col], cy = g_c[n0 + col + 1];
            #pragma unroll
            for (int mi = 0; mi < 4; mi++) {
                const int r0 = wm * 64 + mi * 16 + lr;     // local row
                __half2 o0 = __floats2half2_rn(acc[mi][j][0] + cx, acc[mi][j][1] + cy);
                __half2 o1 = __floats2half2_rn(acc[mi][j][2] + cx, acc[mi][j][3] + cy);
                *(uint32_t*)&sc[r0 * SCSTR + col]       = *(uint32_t*)&o0;
                *(uint32_t*)&sc[(r0 + 8) * SCSTR + col] = *(uint32_t*)&o1;
            }
        }
    }
    __syncthreads();

    {
        const int r = tid >> 1;          // local row 0..127
        const int h = tid & 1;           // 64-col half
        const uint4* rowp = (const uint4*)(sc + r * SCSTR + h * 64);
        uint32_t tp[8] = {0, 0, 0, 0, 0, 0, 0, 0};
        const uint32_t gbase = (uint32_t)(n0 + h * 64);
        #pragma unroll
        for (int q2 = 0; q2 < 8; q2++) {
            uint4 u = rowp[q2];
            uint32_t hw[4] = {u.x, u.y, u.z, u.w};
            #pragma unroll
            for (int p = 0; p < 4; p++) {
                #pragma unroll
                for (int e = 0; e < 2; e++) {
                    uint32_t b16 = e ? (hw[p] >> 16) : (hw[p] & 0xFFFFu);
                    b16 = (b16 & 0x8000u) ? (~b16 & 0xFFFFu) : (b16 | 0x8000u);
                    const uint32_t gcol = gbase + (uint32_t)(q2 * 8 + p * 2 + e);
                    const uint32_t k = (b16 << 13) | (8191u - gcol);
                    if (k > tp[7]) {
                        tp[7] = k;
                        #pragma unroll
                        for (int i = 7; i >= 1; i--) {
                            uint32_t aa = tp[i - 1], bb = tp[i];
                            tp[i - 1] = aa > bb ? aa : bb;
                            tp[i]     = aa > bb ? bb : aa;
                        }
                    }
                }
            }
        }
        uint32_t* dst = g_ckeys + (size_t)(m0 + r) * 1024
                      + (uint32_t)blockIdx.x * 16 + h * 8;
        #pragma unroll
        for (int i = 0; i < 8; i++) dst[i] = tp[i];
    }
}

// ---------------- top-36 per row from 1024 candidate keys ----------------
__global__ __launch_bounds__(256)
void topk_kernel() {
    const int row = blockIdx.x;
    const int tid = threadIdx.x;

    uint4 u = ((const uint4*)(g_ckeys + (size_t)row * 1024))[tid];
    uint32_t pk[4] = {u.x, u.y, u.z, u.w};

    uint32_t live = 0xFu;
    uint32_t best = 0;
    #pragma unroll
    for (int i = 0; i < 4; i++) best = max(best, pk[i]);

    __shared__ uint32_t swarp[8];
    __shared__ uint32_t swin;
    __shared__ int winI[NCAND];

    for (int t = 0; t < NCAND; t++) {
        uint32_t p = best;
        #pragma unroll
        for (int off = 16; off; off >>= 1)
            p = max(p, __shfl_down_sync(0xffffffffu, p, off));
        if ((tid & 31) == 0) swarp[tid >> 5] = p;
        __syncthreads();
        if (tid < 32) {
            uint32_t q = (tid < 8) ? swarp[tid] : 0u;
            #pragma unroll
            for (int off = 4; off; off >>= 1)
                q = max(q, __shfl_down_sync(0xffffffffu, q, off));
            if (tid == 0) { swin = q; winI[t] = (int)(8191u - (q & 0x1FFFu)); }
        }
        __syncthreads();
        const uint32_t w = swin;
        // the unique owner clears its copy and recomputes its local best
        #pragma unroll
        for (int i = 0; i < 4; i++) {
            if ((live >> i) & 1u && pk[i] == w) {
                live &= ~(1u << i);
                best = 0;
                #pragma unroll
                for (int q2 = 0; q2 < 4; q2++)
                    if ((live >> q2) & 1u) best = max(best, pk[q2]);
            }
        }
        __syncthreads();
    }

    if (tid < NCAND) g_cand[(size_t)row * NCAND + tid] = winI[tid];
}

// ---------------- exact fp32 rerank of 36 candidates -> top-30 ----------------
__global__ __launch_bounds__(256)
void rerank_kernel(const float* __restrict__ x,
                   const float* __restrict__ enc_w,
                   float* __restrict__ sparse) {
    __shared__ float4 xs[ND / 4];
    __shared__ float  sc[NCAND];
    __shared__ int    si[NCAND];
    __shared__ int    cnt;
    const int row = blockIdx.x;
    const int tid = threadIdx.x;
    const int wid = tid >> 5, lane = tid & 31;

    xs[tid] = ((const float4*)(x + (size_t)row * ND))[tid];
    if (tid == 0) cnt = 0;
    __syncthreads();

    for (int c = wid; c < NCAND; c += 8) {
        const int f = g_cand[(size_t)row * NCAND + c];
        const float4* wr = (const float4*)(enc_w + (size_t)f * ND);
        float s = 0.f;
        #pragma unroll
        for (int j = lane; j < ND / 4; j += 32) {
            float4 wv = wr[j], xv = xs[j];
            s += wv.x * xv.x + wv.y * xv.y + wv.z * xv.z + wv.w * xv.w;
        }
        #pragma unroll
        for (int off = 16; off; off >>= 1) s += __shfl_down_sync(0xffffffffu, s, off);
        if (lane == 0) { sc[c] = s + g_c[f]; si[c] = f; }
    }
    __syncthreads();

    if (tid < NCAND) {
        const float v = sc[tid];
        const int   f = si[tid];
        int rank = 0;
        #pragma unroll
        for (int j = 0; j < NCAND; j++)
            rank += (sc[j] > v) || (sc[j] == v && si[j] < f);
        if (rank < KTOP) {
            const float rv = fmaxf(v, 0.f);
            sparse[(size_t)row * NF + f] = rv;
            int slot = atomicAdd(&cnt, 1);
            g_wv[(size_t)row * 32 + slot] = rv;
            g_wi[(size_t)row * 32 + slot] = f;
        }
    }
}

// ---------------- decode: recon[row,:] = dec_b + sum_k v_k * dec_wT_h[idx_k,:] ----------------
__global__ __launch_bounds__(256)
void decode_kernel(const float* __restrict__ dec_b, float* __restrict__ recon) {
    __shared__ float sv[KTOP];
    __shared__ int   si[KTOP];
    const int row = blockIdx.x;
    const int tid = threadIdx.x;
    if (tid < KTOP) {
        sv[tid] = g_wv[(size_t)row * 32 + tid];
        si[tid] = g_wi[(size_t)row * 32 + tid];
    }
    __syncthreads();

    const int d = tid * 4;
    float4 acc = *(const float4*)(dec_b + d);
    #pragma unroll 5
    for (int k = 0; k < KTOP; k++) {
        const float v = sv[k];
        const uint2 u = *(const uint2*)(g_dwt_h + (size_t)si[k] * ND + d);
        const float2 w0 = __half22float2(*(const __half2*)&u.x);
        const float2 w1 = __half22float2(*(const __half2*)&u.y);
        acc.x = fmaf(v, w0.x, acc.x);
        acc.y = fmaf(v, w0.y, acc.y);
        acc.z = fmaf(v, w1.x, acc.z);
        acc.w = fmaf(v, w1.y, acc.w);
    }
    *(float4*)(recon + (size_t)row * ND + d) = acc;
}

// ---------------- launch ----------------
extern "C" void kernel_launch(void* const* d_in, const int* in_sizes, int n_in,
                              void* d_out, int out_size) {
    const float* x     = (const float*)d_in[0];
    const float* enc_w = (const float*)d_in[1];
    const float* enc_b = (const float*)d_in[2];
    const float* dec_w = (const float*)d_in[3];
    const float* dec_b = (const float*)d_in[4];

    float* recon  = (float*)d_out;                       // [B, D]
    float* sparse = (float*)d_out + (size_t)NB * ND;     // [B, F]

    cudaFuncSetAttribute(tc_gemm_kernel,
                         cudaFuncAttributeMaxDynamicSharedMemorySize, GEMM_SMEM);

    __nv_bfloat16 *a0, *b0;
    cudaGetSymbolAddress((void**)&a0, g_a0);
    cudaGetSymbolAddress((void**)&b0, g_b0);

    tobf16_kernel<<<2048, 256>>>((const float4*)x, a0, NB * ND / 4);
    prep_encw_kernel<<<NF / 8, 256>>>((const float4*)enc_w, enc_b, dec_b, b0);
    transpose_kernel<<<dim3(NF / 32, ND / 32), dim3(32, 8)>>>(dec_w);

    tc_gemm_kernel<<<dim3(NF / 128, NB / 128), 256, GEMM_SMEM>>>(sparse);

    topk_kernel<<<NB, 256>>>();
    rerank_kernel<<<NB, 256>>>(x, enc_w, sparse);
    decode_kernel<<<NB, 256>>>(dec_b, recon);
}